// round 10
// baseline (speedup 1.0000x reference)
#include <cuda_runtime.h>
#include <math.h>

// ---------------- problem constants ----------------
constexpr int   B_TOT  = 1000000;
constexpr int   SPIN   = 1000;
constexpr int   TRAIN  = 800000;
constexpr float ML     = 2.9086f;
constexpr float SL     = 1.898f;
constexpr float U1MAX  = 221.519f;

// roles / geometry
constexpr int CHUNK  = 32;                     // steps per chunk
constexpr int WARMCH = 2;                      // warm-up chunks (64 steps)
constexpr int NCH    = B_TOT / CHUNK;          // 31250
constexpr int SCB    = 128;                    // chunks per scan block
constexpr int SCANB  = (NCH + SCB - 1) / SCB;  // 245 scan blocks
constexpr int REDB   = 132;                    // reduce blocks
constexpr int PAIRS  = B_TOT / 2;              // 500000
constexpr int BLK    = 256;
constexpr int SWB    = (PAIRS + BLK - 1) / BLK;    // 1954 sweep blocks
constexpr int GRID   = SCANB + REDB + SWB;         // 2331
constexpr int ROWS   = SCB + WARMCH;               // 130

constexpr int SMEM_BYTES = ROWS * 33 * 8;          // 34320 (float2 window)

__device__ int    g_flags[SCANB];
__device__ double g_part[REDB][2];
__device__ int    g_cnt = 0;
__device__ int    g_fin = 0;

// ---------------- math helpers ----------------
__device__ __forceinline__ float tanha(float z) {
    float r;
    asm("tanh.approx.f32 %0, %1;" : "=f"(r) : "f"(z));
    return r;
}

struct P {
    float koo, coo;        // zo = koo*c + coo
    float kib, cib, kibu;  // zi = kib*c + (kibu*u1 + cib)
    float kol, col;        // zl = kol*u2 + col
    float hoo1, hol1;      // 0.5*oo1, 0.5*ol1
};

__device__ __forceinline__ P load_params(
    const float* cmean, const float* cstd,
    const float* wro, const float* wrl, const float* wrf,
    const float* b0o, const float* wb1o,
    const float* b0l, const float* wb2l,
    const float* wb1u, const float* b0u)
{
    P p;
    float mo = cmean[0];
    float inv_so = 1.0f / cstd[0];
    float eo = __expf(wro[0]);
    float el = __expf(wrl[0]);
    float ef = __expf(wrf[0]);
    float id = __fdividef(1.0f, eo + el + ef);
    p.hoo1 = 0.5f * eo * id;
    p.hol1 = 0.5f * el * id;
    float w1o = wb1o[0], w1u = wb1u[0], w2l = wb2l[0];
    p.koo  = 0.5f * w1o * inv_so;
    p.coo  = 0.5f * (b0o[0] - mo * inv_so * w1o);
    p.kib  = 0.5f * w1u * inv_so;
    p.cib  = 0.5f * (b0u[0] - mo * inv_so * w1u);
    p.kibu = 0.5f * w1u / U1MAX;
    p.kol  = 0.5f * w2l / SL;
    p.col  = 0.5f * (b0l[0] - (ML / SL) * w2l);
    return p;
}

// one recurrence step (state only). chain: fma -> tanh -> fma -> fma.
__device__ __forceinline__ float step_c(float c, float u1, float u2, const P& p) {
    float hu1 = 0.5f * u1;
    float zib = fmaf(u1, p.kibu, p.cib);
    float zl  = fmaf(u2, p.kol, p.col);
    float ol  = fmaf(tanha(zl), p.hol1, p.hol1);
    float zo  = fmaf(c, p.koo, p.coo);
    float zi  = fmaf(c, p.kib, zib);
    float to  = tanha(zo);
    float ti  = tanha(zi);
    float hc  = p.hoo1 * c;
    float olc_c = ol * c;
    float L   = (c > 0.0f) ? fminf(olc_c, u2) : olc_c;
    float base = ((c - hc) + hu1) - L;
    return fmaf(-hu1, ti, fmaf(-hc, to, base));
}

// ---------------- the unified kernel ---------------------------------------
__global__ __launch_bounds__(BLK) void fused_k(
    const float4* __restrict__ x4,
    float* __restrict__ out,
    const int* __restrict__ time_lag_p,
    const float* __restrict__ y_obs,
    const float* cmean, const float* cstd,
    const float* wro, const float* wrl, const float* wrf,
    const float* b0o, const float* wb1o,
    const float* b0l, const float* wb2l,
    const float* wb1u, const float* b0u)
{
    const int tid = threadIdx.x;
    const int bid = blockIdx.x;
    const size_t B = (size_t)B_TOT;
    float* c_out = out + B;                    // c_n slot doubles as c scratch

    if (bid < SCANB) {
        // ===================== scan block ==================================
        extern __shared__ char smem_raw[];
        float2 (*sx)[33] = reinterpret_cast<float2(*)[33]>(smem_raw);

        const int b0 = bid * SCB;
        const int base_t = (b0 - WARMCH) * CHUNK;
        const P p = load_params(cmean, cstd, wro, wrl, wrf, b0o, wb1o, b0l, wb2l, wb1u, b0u);

        // stage window with all 256 threads
        constexpr int NLD4 = ROWS * CHUNK / 2;          // 2080
        #pragma unroll 4
        for (int i = tid; i < NLD4; i += BLK) {
            int t = base_t + 2 * i;
            float4 v = make_float4(0.f, 0.f, 0.f, 0.f);
            if (t >= 0 && t < B_TOT) v = __ldg(x4 + (t >> 1));
            int li = 2 * i;
            int row = li >> 5, s = li & 31;
            sx[row][s]     = make_float2(v.x, v.y);
            sx[row][s + 1] = make_float2(v.z, v.w);
        }
        __syncthreads();

        // recurrence on first 128 threads (1 thread = 1 chunk)
        if (tid < SCB) {
            const int chunk = b0 + tid;
            const int row   = tid + WARMCH;
            if (chunk < NCH) {
                float c = 0.0f;
                #pragma unroll
                for (int d = WARMCH; d >= 1; --d) {
                    if (chunk - d >= 0) {
                        #pragma unroll 8
                        for (int s = 0; s < CHUNK; ++s) {
                            float2 u = sx[row - d][s];
                            c = step_c(c, u.x, u.y, p);
                        }
                    }
                }
                #pragma unroll 8
                for (int s = 0; s < CHUNK; ++s) {
                    float2 u = sx[row][s];
                    sx[row][s].x = c;                   // pre-update state
                    c = step_c(c, u.x, u.y, p);
                }
            }
        }
        __syncthreads();

        // write c trajectory coalesced with all 256 threads
        const int t0 = b0 * CHUNK;
        #pragma unroll 4
        for (int i = tid; i < SCB * CHUNK; i += BLK) {
            int t = t0 + i;
            if (t < B_TOT) c_out[t] = sx[(i >> 5) + WARMCH][i & 31].x;
        }
        __threadfence();
        __syncthreads();
        if (tid == 0) atomicExch(&g_flags[bid], 1);

    } else if (bid < SCANB + REDB) {
        // ===================== reduce block ================================
        __shared__ double shred[2][BLK / 32];
        const int rbid = bid - SCANB;
        const float4* y4 = reinterpret_cast<const float4*>(y_obs + SPIN);
        const int n4 = (TRAIN - SPIN) / 4;
        double s = 0.0, s2 = 0.0;
        for (int i = rbid * BLK + tid; i < n4; i += REDB * BLK) {
            float4 v = __ldg(y4 + i);
            double a = v.x, b = v.y, cc = v.z, d = v.w;
            s  += (a + b) + (cc + d);
            s2 += (a * a + b * b) + (cc * cc + d * d);
        }
        #pragma unroll
        for (int o = 16; o > 0; o >>= 1) {
            s  += __shfl_down_sync(0xffffffffu, s,  o);
            s2 += __shfl_down_sync(0xffffffffu, s2, o);
        }
        int lane = tid & 31, warp = tid >> 5;
        if (lane == 0) { shred[0][warp] = s; shred[1][warp] = s2; }
        __syncthreads();
        if (tid == 0) {
            s = 0.0; s2 = 0.0;
            #pragma unroll
            for (int w = 0; w < BLK / 32; ++w) { s += shred[0][w]; s2 += shred[1][w]; }
            g_part[rbid][0] = s;
            g_part[rbid][1] = s2;
            __threadfence();
            atomicAdd(&g_cnt, 1);
        }

    } else {
        // ===================== sweep block =================================
        __shared__ float s_os;
        const int sb = bid - SCANB - REDB;
        const int i  = sb * BLK + tid;                 // pair index
        const bool act = (i < PAIRS);

        const P p = load_params(cmean, cstd, wro, wrl, wrf, b0o, wb1o, b0l, wb2l, wb1u, b0u);
        const int tl = time_lag_p[0];

        float4 xa = make_float4(0.f, 0.f, 0.f, 0.f);
        if (act) xa = __ldg(x4 + i);

        // warp 0: wait for reduce partials, fold obsstd
        if (tid < 32) {
            if (tid == 0) {
                while (atomicAdd(&g_cnt, 0) < REDB) __nanosleep(128);
            }
            __syncwarp();
            __threadfence();
            double s = 0.0, s2 = 0.0;
            for (int k = tid; k < REDB; k += 32) {
                s  += g_part[k][0];
                s2 += g_part[k][1];
            }
            #pragma unroll
            for (int o = 16; o > 0; o >>= 1) {
                s  += __shfl_down_sync(0xffffffffu, s,  o);
                s2 += __shfl_down_sync(0xffffffffu, s2, o);
            }
            if (tid == 0) {
                double n = (double)(TRAIN - SPIN);
                s_os = (float)sqrt((s2 - s * s / n) / (n - 1.0));
            }
        }
        // warp 1 lane 0: wait for this segment's scan block
        if (tid == 32) {
            while (atomicAdd(&g_flags[sb >> 3], 0) == 0) __nanosleep(128);
        }
        __syncthreads();
        __threadfence();

        if (act) {
            const float os = s_os;
            float2 c2 = __ldcg(reinterpret_cast<const float2*>(out + B) + i);

            float cv[2]  = {c2.x, c2.y};
            float u1v[2] = {xa.x, xa.z};
            float u2v[2] = {xa.y, xa.w};

            float2 vh, vc, vl, vlc, vbp, vib, voo, vol, volc, vf, vos;
            float* ph = &vh.x;  float* pc = &vc.x;  float* pl = &vl.x;
            float* plc = &vlc.x; float* pbp = &vbp.x; float* pib = &vib.x;
            float* poo = &voo.x; float* pol = &vol.x; float* polc = &volc.x;
            float* pf = &vf.x;   float* pos = &vos.x;

            int t0 = 2 * i;
            #pragma unroll
            for (int j = 0; j < 2; ++j) {
                float c = cv[j], u1 = u1v[j], u2 = u2v[j];
                float zo = fmaf(c, p.koo, p.coo);
                float zi = fmaf(c, p.kib, fmaf(u1, p.kibu, p.cib));
                float zl = fmaf(u2, p.kol, p.col);
                float oo = fmaf(tanha(zo), p.hoo1, p.hoo1);
                float ib = fmaf(tanha(zi), 0.5f, 0.5f);
                float ol = fmaf(tanha(zl), p.hol1, p.hol1);
                bool  cp = (c > 0.0f);
                float olc  = cp ? fminf(ol, __fdividef(u2, c)) : ol;
                float olcc = cp ? fminf(ol * c, u2) : ol * c;
                float f   = 1.0f - oo - olc;
                float m   = (t0 + j >= tl) ? 1.0f : 0.0f;
                float bp  = ib * u1;
                float h   = fmaf(oo, c, bp);
                ph[j]   = m * h;
                pc[j]   = m * c;
                pl[j]   = m * (ol * c);
                plc[j]  = m * olcc;
                pbp[j]  = m * bp;
                pib[j]  = m * ib;
                poo[j]  = m * oo;
                pol[j]  = m * ol;
                polc[j] = m * olc;
                pf[j]   = m * f;
                pos[j]  = m * os;
            }

            reinterpret_cast<float2*>(out)[i]          = vh;
            if (tl != 0)                                  // tl==0: scan's write IS m*c
                reinterpret_cast<float2*>(out + B)[i]  = vc;
            reinterpret_cast<float2*>(out + 2 * B)[i]  = vl;
            reinterpret_cast<float2*>(out + 3 * B)[i]  = vlc;
            reinterpret_cast<float2*>(out + 4 * B)[i]  = vbp;
            reinterpret_cast<float2*>(out + 5 * B)[i]  = vib;
            reinterpret_cast<float2*>(out + 6 * B)[i]  = voo;
            reinterpret_cast<float2*>(out + 7 * B)[i]  = vol;
            reinterpret_cast<float2*>(out + 8 * B)[i]  = volc;
            reinterpret_cast<float2*>(out + 9 * B)[i]  = vf;
            reinterpret_cast<float4*>(out + 10 * B)[i] =
                make_float4(ph[0], pos[0], ph[1], pos[1]);
            reinterpret_cast<float2*>(out + 12 * B)[i] = vos;
        }
    }

    // ---- epilogue: last block resets counters/flags for next replay ----
    __syncthreads();
    __shared__ int s_last;
    if (tid == 0) s_last = (atomicAdd(&g_fin, 1) == GRID - 1) ? 1 : 0;
    __syncthreads();
    if (s_last) {
        for (int k = tid; k < SCANB; k += BLK) g_flags[k] = 0;
        if (tid == 0) { g_cnt = 0; g_fin = 0; }
    }
}

// ---------------- launch ----------------
extern "C" void kernel_launch(void* const* d_in, const int* in_sizes, int n_in,
                              void* d_out, int out_size) {
    const float4* x4    = (const float4*)d_in[0];
    const int*    tl    = (const int*)   d_in[2];
    const float*  y_obs = (const float*) d_in[3];
    const float*  cmean = (const float*) d_in[4];
    const float*  cstd  = (const float*) d_in[5];
    const float*  wro   = (const float*) d_in[6];
    const float*  wrl   = (const float*) d_in[7];
    const float*  wrf   = (const float*) d_in[8];
    const float*  b0o   = (const float*) d_in[9];
    const float*  wb1o  = (const float*) d_in[10];
    const float*  b0l   = (const float*) d_in[11];
    const float*  wb2l  = (const float*) d_in[12];
    const float*  wb1u  = (const float*) d_in[13];
    const float*  b0u   = (const float*) d_in[14];
    float* out = (float*)d_out;

    cudaFuncSetAttribute(fused_k, cudaFuncAttributeMaxDynamicSharedMemorySize,
                         SMEM_BYTES);

    fused_k<<<GRID, BLK, SMEM_BYTES>>>(x4, out, tl, y_obs,
        cmean, cstd, wro, wrl, wrf, b0o, wb1o, b0l, wb2l, wb1u, b0u);
}

// round 11
// speedup vs baseline: 1.2711x; 1.2711x over previous
#include <cuda_runtime.h>
#include <math.h>

// ---------------- problem constants ----------------
constexpr int   B_TOT  = 1000000;
constexpr int   SPIN   = 1000;
constexpr int   TRAIN  = 800000;
constexpr float ML     = 2.9086f;
constexpr float SL     = 1.898f;
constexpr float U1MAX  = 221.519f;

// chunked-scan parameters
constexpr int CHUNK   = 32;                   // steps per chunk
constexpr int WARMCH  = 2;                    // warm-up chunks (64 steps)
constexpr int NCH     = B_TOT / CHUNK;        // 31250 (exact)
constexpr int SCB     = 128;                  // chunks per scan block
constexpr int SBLK    = 256;                  // threads per block (both kernels)
constexpr int SGRID   = (NCH + SCB - 1) / SCB;   // 245 scan blocks

constexpr int RBLOCKS = 132;
__device__ double g_part[RBLOCKS][2];

// ---------------- math helpers ----------------
__device__ __forceinline__ float tanha(float z) {
    float r;
    asm("tanh.approx.f32 %0, %1;" : "=f"(r) : "f"(z));
    return r;
}

__device__ __forceinline__ void stcs2(float* p, float2 v) {
    asm volatile("st.global.cs.v2.f32 [%0], {%1, %2};" :: "l"(p), "f"(v.x), "f"(v.y) : "memory");
}
__device__ __forceinline__ void stcs4(float* p, float4 v) {
    asm volatile("st.global.cs.v4.f32 [%0], {%1, %2, %3, %4};"
                 :: "l"(p), "f"(v.x), "f"(v.y), "f"(v.z), "f"(v.w) : "memory");
}

struct P {
    float koo, coo;        // zo = koo*c + coo
    float kib, cib, kibu;  // zi = kib*c + (kibu*u1 + cib)
    float kol, col;        // zl = kol*u2 + col
    float hoo1, hol1;      // 0.5*oo1, 0.5*ol1
};

__device__ __forceinline__ P load_params(
    const float* cmean, const float* cstd,
    const float* wro, const float* wrl, const float* wrf,
    const float* b0o, const float* wb1o,
    const float* b0l, const float* wb2l,
    const float* wb1u, const float* b0u)
{
    P p;
    float mo = cmean[0];
    float inv_so = 1.0f / cstd[0];
    float eo = __expf(wro[0]);
    float el = __expf(wrl[0]);
    float ef = __expf(wrf[0]);
    float id = __fdividef(1.0f, eo + el + ef);
    p.hoo1 = 0.5f * eo * id;
    p.hol1 = 0.5f * el * id;
    float w1o = wb1o[0], w1u = wb1u[0], w2l = wb2l[0];
    p.koo  = 0.5f * w1o * inv_so;
    p.coo  = 0.5f * (b0o[0] - mo * inv_so * w1o);
    p.kib  = 0.5f * w1u * inv_so;
    p.cib  = 0.5f * (b0u[0] - mo * inv_so * w1u);
    p.kibu = 0.5f * w1u / U1MAX;
    p.kol  = 0.5f * w2l / SL;
    p.col  = 0.5f * (b0l[0] - (ML / SL) * w2l);
    return p;
}

// one recurrence step (state only). chain: fma -> tanh -> fma -> fma.
__device__ __forceinline__ float step_c(float c, float u1, float u2, const P& p) {
    float hu1 = 0.5f * u1;
    float zib = fmaf(u1, p.kibu, p.cib);
    float zl  = fmaf(u2, p.kol, p.col);
    float ol  = fmaf(tanha(zl), p.hol1, p.hol1);
    float zo  = fmaf(c, p.koo, p.coo);
    float zi  = fmaf(c, p.kib, zib);
    float to  = tanha(zo);
    float ti  = tanha(zi);
    float hc  = p.hoo1 * c;
    float olc_c = ol * c;
    float L   = (c > 0.0f) ? fminf(olc_c, u2) : olc_c;
    float base = ((c - hc) + hu1) - L;
    return fmaf(-hu1, ti, fmaf(-hc, to, base));
}

// ---------------- kernel A: fused scan + reduction partials ---------------
// Blocks [0, SGRID): scan (256 threads stage/writeback, 128 run recurrence).
// Blocks [SGRID, SGRID+RBLOCKS): sum/sumsq partials over y_obs[SPIN:TRAIN].
__global__ __launch_bounds__(SBLK) void scanreduce_k(
    const float4* __restrict__ x4,
    float* __restrict__ c_out,
    const float* __restrict__ y_obs,
    const float* cmean, const float* cstd,
    const float* wro, const float* wrl, const float* wrf,
    const float* b0o, const float* wb1o,
    const float* b0l, const float* wb2l,
    const float* wb1u, const float* b0u)
{
    __shared__ float2 sx[SCB + WARMCH][CHUNK + 1];   // 130 x 33 float2 = 34.3KB
    __shared__ double shred[2][SBLK / 32];

    const int tid = threadIdx.x;

    if (blockIdx.x >= SGRID) {
        // ---------------- reduction branch ----------------
        const int rbid = blockIdx.x - SGRID;
        const float4* y4 = reinterpret_cast<const float4*>(y_obs + SPIN);
        const int n4 = (TRAIN - SPIN) / 4;
        double s = 0.0, s2 = 0.0;
        int stride = RBLOCKS * SBLK;
        for (int i = rbid * SBLK + tid; i < n4; i += stride) {
            float4 v = __ldg(y4 + i);
            double a = v.x, b = v.y, cc = v.z, d = v.w;
            s  += (a + b) + (cc + d);
            s2 += (a * a + b * b) + (cc * cc + d * d);
        }
        #pragma unroll
        for (int o = 16; o > 0; o >>= 1) {
            s  += __shfl_down_sync(0xffffffffu, s,  o);
            s2 += __shfl_down_sync(0xffffffffu, s2, o);
        }
        int lane = tid & 31, warp = tid >> 5;
        if (lane == 0) { shred[0][warp] = s; shred[1][warp] = s2; }
        __syncthreads();
        if (tid == 0) {
            s = 0.0; s2 = 0.0;
            #pragma unroll
            for (int w = 0; w < SBLK / 32; ++w) { s += shred[0][w]; s2 += shred[1][w]; }
            g_part[rbid][0] = s;
            g_part[rbid][1] = s2;
        }
        return;
    }

    // ---------------- scan branch ----------------
    const int b0  = blockIdx.x * SCB;                  // first owned chunk
    const int base_t = (b0 - WARMCH) * CHUNK;          // window start (may be <0)

    const P p = load_params(cmean, cstd, wro, wrl, wrf, b0o, wb1o, b0l, wb2l, wb1u, b0u);

    // stage window: (SCB+WARMCH)*CHUNK timesteps, 2 per float4 — 256 threads
    constexpr int NLD4 = (SCB + WARMCH) * CHUNK / 2;   // 2080
    #pragma unroll 4
    for (int i = tid; i < NLD4; i += SBLK) {
        int t = base_t + 2 * i;
        float4 v = make_float4(0.f, 0.f, 0.f, 0.f);
        if (t >= 0 && t < B_TOT) v = __ldg(x4 + (t >> 1));
        int li = 2 * i;                                // local timestep
        int row = li >> 5, s = li & 31;
        sx[row][s]     = make_float2(v.x, v.y);
        sx[row][s + 1] = make_float2(v.z, v.w);
    }
    __syncthreads();

    // recurrence: first 128 threads, 1 thread = 1 chunk
    if (tid < SCB) {
        const int chunk = b0 + tid;
        const int row   = tid + WARMCH;                // own SMEM row
        if (chunk < NCH) {
            float c = 0.0f;
            #pragma unroll
            for (int d = WARMCH; d >= 1; --d) {
                if (chunk - d >= 0) {
                    #pragma unroll 8
                    for (int s = 0; s < CHUNK; ++s) {
                        float2 u = sx[row - d][s];
                        c = step_c(c, u.x, u.y, p);
                    }
                }
            }
            #pragma unroll 8
            for (int s = 0; s < CHUNK; ++s) {
                float2 u = sx[row][s];
                sx[row][s].x = c;                      // record pre-update state
                c = step_c(c, u.x, u.y, p);
            }
        }
    }
    __syncthreads();

    // coalesced write-back of c trajectory — 256 threads
    const int t0 = b0 * CHUNK;
    #pragma unroll 4
    for (int i = tid; i < SCB * CHUNK; i += SBLK) {
        int t = t0 + i;
        if (t < B_TOT) c_out[t] = sx[(i >> 5) + WARMCH][i & 31].x;
    }
}

// ---------------- kernel B: pointwise outputs, 2 timesteps/thread ---------
__global__ __launch_bounds__(256) void point_k(
    const float4* __restrict__ x4,        // x as float4: exactly 2 timesteps
    float* __restrict__ out,
    const int* __restrict__ time_lag_p,
    const float* cmean, const float* cstd,
    const float* wro, const float* wrl, const float* wrf,
    const float* b0o, const float* wb1o,
    const float* b0l, const float* wb2l,
    const float* wb1u, const float* b0u)
{
    __shared__ float s_os;

    // warp 0: fold the RBLOCKS partials into obsstd (ddof=1)
    if (threadIdx.x < 32) {
        int lane = threadIdx.x;
        double s = 0.0, s2 = 0.0;
        for (int i = lane; i < RBLOCKS; i += 32) {
            s  += g_part[i][0];
            s2 += g_part[i][1];
        }
        #pragma unroll
        for (int o = 16; o > 0; o >>= 1) {
            s  += __shfl_down_sync(0xffffffffu, s,  o);
            s2 += __shfl_down_sync(0xffffffffu, s2, o);
        }
        if (lane == 0) {
            double n = (double)(TRAIN - SPIN);
            s_os = (float)sqrt((s2 - s * s / n) / (n - 1.0));
        }
    }

    int i = blockIdx.x * blockDim.x + threadIdx.x;     // pair index
    bool act = (i < B_TOT / 2);

    const P p = load_params(cmean, cstd, wro, wrl, wrf, b0o, wb1o, b0l, wb2l, wb1u, b0u);
    const int tl = time_lag_p[0];
    const size_t B = (size_t)B_TOT;

    // hoisted loads: one float2 (c pair) + one float4 (x pair)
    float2 c2 = make_float2(0.f, 0.f);
    float4 xa = make_float4(0.f, 0.f, 0.f, 0.f);
    if (act) {
        c2 = __ldg(reinterpret_cast<const float2*>(out + B) + i);
        xa = __ldg(x4 + i);
    }

    __syncthreads();
    const float os = s_os;
    if (!act) return;

    float cv[2]  = {c2.x, c2.y};
    float u1v[2] = {xa.x, xa.z};
    float u2v[2] = {xa.y, xa.w};

    float2 vh, vc, vl, vlc, vbp, vib, voo, vol, volc, vf, vos;
    float* ph = &vh.x;  float* pc = &vc.x;  float* pl = &vl.x;  float* plc = &vlc.x;
    float* pbp = &vbp.x; float* pib = &vib.x; float* poo = &voo.x;
    float* pol = &vol.x; float* polc = &volc.x; float* pf = &vf.x; float* pos = &vos.x;

    int t0 = 2 * i;
    #pragma unroll
    for (int j = 0; j < 2; ++j) {
        float c = cv[j], u1 = u1v[j], u2 = u2v[j];
        float zo = fmaf(c, p.koo, p.coo);
        float zi = fmaf(c, p.kib, fmaf(u1, p.kibu, p.cib));
        float zl = fmaf(u2, p.kol, p.col);
        float oo = fmaf(tanha(zo), p.hoo1, p.hoo1);
        float ib = fmaf(tanha(zi), 0.5f, 0.5f);
        float ol = fmaf(tanha(zl), p.hol1, p.hol1);
        bool  cp = (c > 0.0f);
        float olc  = cp ? fminf(ol, __fdividef(u2, c)) : ol;
        float olcc = cp ? fminf(ol * c, u2) : ol * c;
        float f   = 1.0f - oo - olc;
        float m   = (t0 + j >= tl) ? 1.0f : 0.0f;
        float bp  = ib * u1;
        float h   = fmaf(oo, c, bp);
        ph[j]   = m * h;
        pc[j]   = m * c;
        pl[j]   = m * (ol * c);
        plc[j]  = m * olcc;
        pbp[j]  = m * bp;
        pib[j]  = m * ib;
        poo[j]  = m * oo;
        pol[j]  = m * ol;
        polc[j] = m * olc;
        pf[j]   = m * f;
        pos[j]  = m * os;
    }

    stcs2(out + 2 * (size_t)i, vh);
    if (tl != 0)                                   // tl==0: scan's write IS m*c
        stcs2(out + B + 2 * (size_t)i, vc);
    stcs2(out + 2 * B + 2 * (size_t)i,  vl);
    stcs2(out + 3 * B + 2 * (size_t)i,  vlc);
    stcs2(out + 4 * B + 2 * (size_t)i,  vbp);
    stcs2(out + 5 * B + 2 * (size_t)i,  vib);
    stcs2(out + 6 * B + 2 * (size_t)i,  voo);
    stcs2(out + 7 * B + 2 * (size_t)i,  vol);
    stcs2(out + 8 * B + 2 * (size_t)i,  volc);
    stcs2(out + 9 * B + 2 * (size_t)i,  vf);
    stcs4(out + 10 * B + 4 * (size_t)i, make_float4(ph[0], pos[0], ph[1], pos[1]));
    stcs2(out + 12 * B + 2 * (size_t)i, vos);
}

// ---------------- launch ----------------
extern "C" void kernel_launch(void* const* d_in, const int* in_sizes, int n_in,
                              void* d_out, int out_size) {
    const float4* x4    = (const float4*)d_in[0];
    const int*    tl    = (const int*)   d_in[2];
    const float*  y_obs = (const float*) d_in[3];
    const float*  cmean = (const float*) d_in[4];
    const float*  cstd  = (const float*) d_in[5];
    const float*  wro   = (const float*) d_in[6];
    const float*  wrl   = (const float*) d_in[7];
    const float*  wrf   = (const float*) d_in[8];
    const float*  b0o   = (const float*) d_in[9];
    const float*  wb1o  = (const float*) d_in[10];
    const float*  b0l   = (const float*) d_in[11];
    const float*  wb2l  = (const float*) d_in[12];
    const float*  wb1u  = (const float*) d_in[13];
    const float*  b0u   = (const float*) d_in[14];
    float* out = (float*)d_out;

    float* c_out = out + (size_t)B_TOT;                   // stash c in c_n slot
    scanreduce_k<<<SGRID + RBLOCKS, SBLK>>>(x4, c_out, y_obs,
        cmean, cstd, wro, wrl, wrf, b0o, wb1o, b0l, wb2l, wb1u, b0u);

    point_k<<<(B_TOT / 2 + 255) / 256, 256>>>(
        x4, out, tl,
        cmean, cstd, wro, wrl, wrf, b0o, wb1o, b0l, wb2l, wb1u, b0u);
}

// round 12
// speedup vs baseline: 1.4410x; 1.1337x over previous
#include <cuda_runtime.h>
#include <math.h>

// ---------------- problem constants ----------------
constexpr int   B_TOT  = 1000000;
constexpr int   SPIN   = 1000;
constexpr int   TRAIN  = 800000;
constexpr float ML     = 2.9086f;
constexpr float SL     = 1.898f;
constexpr float U1MAX  = 221.519f;

// chunked-scan parameters
constexpr int CHUNK   = 32;                   // steps per chunk
constexpr int WARMCH  = 2;                    // warm-up chunks (64 steps)
constexpr int NCH     = B_TOT / CHUNK;        // 31250 (exact)
constexpr int SCB     = 128;                  // chunks per scan block
constexpr int SBLK    = 256;                  // threads per block (both kernels)
constexpr int SGRID   = (NCH + SCB - 1) / SCB;   // 245 scan blocks

constexpr int RBLOCKS = 132;
__device__ double g_part[RBLOCKS][2];
__device__ int    g_rcnt = 0;                 // reduce-done counter (self-resetting)
__device__ float  g_obsstd;

// ---------------- math helpers ----------------
__device__ __forceinline__ float tanha(float z) {
    float r;
    asm("tanh.approx.f32 %0, %1;" : "=f"(r) : "f"(z));
    return r;
}

__device__ __forceinline__ void stcs2(float* p, float2 v) {
    asm volatile("st.global.cs.v2.f32 [%0], {%1, %2};" :: "l"(p), "f"(v.x), "f"(v.y) : "memory");
}
__device__ __forceinline__ void stcs4(float* p, float4 v) {
    asm volatile("st.global.cs.v4.f32 [%0], {%1, %2, %3, %4};"
                 :: "l"(p), "f"(v.x), "f"(v.y), "f"(v.z), "f"(v.w) : "memory");
}

struct P {
    float koo, coo;        // zo = koo*c + coo
    float kib, cib, kibu;  // zi = kib*c + (kibu*u1 + cib)
    float kol, col;        // zl = kol*u2 + col
    float hoo1, hol1;      // 0.5*oo1, 0.5*ol1
};

__device__ __forceinline__ P load_params(
    const float* cmean, const float* cstd,
    const float* wro, const float* wrl, const float* wrf,
    const float* b0o, const float* wb1o,
    const float* b0l, const float* wb2l,
    const float* wb1u, const float* b0u)
{
    P p;
    float mo = cmean[0];
    float inv_so = 1.0f / cstd[0];
    float eo = __expf(wro[0]);
    float el = __expf(wrl[0]);
    float ef = __expf(wrf[0]);
    float id = __fdividef(1.0f, eo + el + ef);
    p.hoo1 = 0.5f * eo * id;
    p.hol1 = 0.5f * el * id;
    float w1o = wb1o[0], w1u = wb1u[0], w2l = wb2l[0];
    p.koo  = 0.5f * w1o * inv_so;
    p.coo  = 0.5f * (b0o[0] - mo * inv_so * w1o);
    p.kib  = 0.5f * w1u * inv_so;
    p.cib  = 0.5f * (b0u[0] - mo * inv_so * w1u);
    p.kibu = 0.5f * w1u / U1MAX;
    p.kol  = 0.5f * w2l / SL;
    p.col  = 0.5f * (b0l[0] - (ML / SL) * w2l);
    return p;
}

// one recurrence step (state only). chain: fma -> tanh -> fma -> fma.
__device__ __forceinline__ float step_c(float c, float u1, float u2, const P& p) {
    float hu1 = 0.5f * u1;
    float zib = fmaf(u1, p.kibu, p.cib);
    float zl  = fmaf(u2, p.kol, p.col);
    float ol  = fmaf(tanha(zl), p.hol1, p.hol1);
    float zo  = fmaf(c, p.koo, p.coo);
    float zi  = fmaf(c, p.kib, zib);
    float to  = tanha(zo);
    float ti  = tanha(zi);
    float hc  = p.hoo1 * c;
    float olc_c = ol * c;
    float L   = (c > 0.0f) ? fminf(olc_c, u2) : olc_c;
    float base = ((c - hc) + hu1) - L;
    return fmaf(-hu1, ti, fmaf(-hc, to, base));
}

// ---------------- kernel A: fused scan + reduction (+ final obsstd fold) --
__global__ __launch_bounds__(SBLK) void scanreduce_k(
    const float4* __restrict__ x4,
    float* __restrict__ c_out,
    const float* __restrict__ y_obs,
    const float* cmean, const float* cstd,
    const float* wro, const float* wrl, const float* wrf,
    const float* b0o, const float* wb1o,
    const float* b0l, const float* wb2l,
    const float* wb1u, const float* b0u)
{
    __shared__ float2 sx[SCB + WARMCH][CHUNK + 1];   // 130 x 33 float2 = 34.3KB
    __shared__ double shred[2][SBLK / 32];
    __shared__ int s_last;

    const int tid = threadIdx.x;

    if (blockIdx.x >= SGRID) {
        // ---------------- reduction branch ----------------
        const int rbid = blockIdx.x - SGRID;
        const float4* y4 = reinterpret_cast<const float4*>(y_obs + SPIN);
        const int n4 = (TRAIN - SPIN) / 4;
        double s = 0.0, s2 = 0.0;
        int stride = RBLOCKS * SBLK;
        for (int i = rbid * SBLK + tid; i < n4; i += stride) {
            float4 v = __ldg(y4 + i);
            double a = v.x, b = v.y, cc = v.z, d = v.w;
            s  += (a + b) + (cc + d);
            s2 += (a * a + b * b) + (cc * cc + d * d);
        }
        #pragma unroll
        for (int o = 16; o > 0; o >>= 1) {
            s  += __shfl_down_sync(0xffffffffu, s,  o);
            s2 += __shfl_down_sync(0xffffffffu, s2, o);
        }
        int lane = tid & 31, warp = tid >> 5;
        if (lane == 0) { shred[0][warp] = s; shred[1][warp] = s2; }
        __syncthreads();
        if (tid == 0) {
            s = 0.0; s2 = 0.0;
            #pragma unroll
            for (int w = 0; w < SBLK / 32; ++w) { s += shred[0][w]; s2 += shred[1][w]; }
            g_part[rbid][0] = s;
            g_part[rbid][1] = s2;
            __threadfence();
            s_last = (atomicAdd(&g_rcnt, 1) == RBLOCKS - 1) ? 1 : 0;
        }
        __syncthreads();
        // last reduce block folds the partials once and publishes g_obsstd
        if (s_last && tid < 32) {
            __threadfence();
            double s = 0.0, s2 = 0.0;
            for (int i = tid; i < RBLOCKS; i += 32) {
                s  += g_part[i][0];
                s2 += g_part[i][1];
            }
            #pragma unroll
            for (int o = 16; o > 0; o >>= 1) {
                s  += __shfl_down_sync(0xffffffffu, s,  o);
                s2 += __shfl_down_sync(0xffffffffu, s2, o);
            }
            if (tid == 0) {
                double n = (double)(TRAIN - SPIN);
                g_obsstd = (float)sqrt((s2 - s * s / n) / (n - 1.0));
                g_rcnt = 0;                               // reset for next replay
            }
        }
        cudaTriggerProgrammaticLaunchCompletion();
        return;
    }

    // ---------------- scan branch ----------------
    const int b0  = blockIdx.x * SCB;                  // first owned chunk
    const int base_t = (b0 - WARMCH) * CHUNK;          // window start (may be <0)

    const P p = load_params(cmean, cstd, wro, wrl, wrf, b0o, wb1o, b0l, wb2l, wb1u, b0u);

    // stage window: (SCB+WARMCH)*CHUNK timesteps, 2 per float4 — 256 threads
    constexpr int NLD4 = (SCB + WARMCH) * CHUNK / 2;   // 2080
    #pragma unroll 4
    for (int i = tid; i < NLD4; i += SBLK) {
        int t = base_t + 2 * i;
        float4 v = make_float4(0.f, 0.f, 0.f, 0.f);
        if (t >= 0 && t < B_TOT) v = __ldg(x4 + (t >> 1));
        int li = 2 * i;                                // local timestep
        int row = li >> 5, s = li & 31;
        sx[row][s]     = make_float2(v.x, v.y);
        sx[row][s + 1] = make_float2(v.z, v.w);
    }
    __syncthreads();

    // recurrence: first 128 threads, 1 thread = 1 chunk
    if (tid < SCB) {
        const int chunk = b0 + tid;
        const int row   = tid + WARMCH;                // own SMEM row
        if (chunk < NCH) {
            float c = 0.0f;
            #pragma unroll
            for (int d = WARMCH; d >= 1; --d) {
                if (chunk - d >= 0) {
                    #pragma unroll 8
                    for (int s = 0; s < CHUNK; ++s) {
                        float2 u = sx[row - d][s];
                        c = step_c(c, u.x, u.y, p);
                    }
                }
            }
            #pragma unroll 8
            for (int s = 0; s < CHUNK; ++s) {
                float2 u = sx[row][s];
                sx[row][s].x = c;                      // record pre-update state
                c = step_c(c, u.x, u.y, p);
            }
        }
    }
    __syncthreads();

    // compute done — let the dependent grid launch while we drain stores
    cudaTriggerProgrammaticLaunchCompletion();

    // coalesced write-back of c trajectory — 256 threads
    const int t0 = b0 * CHUNK;
    #pragma unroll 4
    for (int i = tid; i < SCB * CHUNK; i += SBLK) {
        int t = t0 + i;
        if (t < B_TOT) c_out[t] = sx[(i >> 5) + WARMCH][i & 31].x;
    }
}

// ---------------- kernel B: pointwise outputs, 2 timesteps/thread ---------
__global__ __launch_bounds__(256) void point_k(
    const float4* __restrict__ x4,        // x as float4: exactly 2 timesteps
    float* __restrict__ out,
    const int* __restrict__ time_lag_p,
    const float* cmean, const float* cstd,
    const float* wro, const float* wrl, const float* wrf,
    const float* b0o, const float* wb1o,
    const float* b0l, const float* wb2l,
    const float* wb1u, const float* b0u)
{
    int i = blockIdx.x * blockDim.x + threadIdx.x;     // pair index
    bool act = (i < B_TOT / 2);

    const P p = load_params(cmean, cstd, wro, wrl, wrf, b0o, wb1o, b0l, wb2l, wb1u, b0u);
    const size_t B = (size_t)B_TOT;

    // independent prefetch (overlaps with primary grid's tail under PDL)
    float4 xa = make_float4(0.f, 0.f, 0.f, 0.f);
    if (act) xa = __ldg(x4 + i);
    const int tl = __ldg(time_lag_p);

    // wait for scanreduce's memory (c trajectory + g_obsstd) to be visible
    cudaGridDependencySynchronize();

    if (!act) return;
    const float os = g_obsstd;
    float2 c2 = __ldg(reinterpret_cast<const float2*>(out + B) + i);

    float cv[2]  = {c2.x, c2.y};
    float u1v[2] = {xa.x, xa.z};
    float u2v[2] = {xa.y, xa.w};

    float2 vh, vc, vl, vlc, vbp, vib, voo, vol, volc, vf, vos;
    float* ph = &vh.x;  float* pc = &vc.x;  float* pl = &vl.x;  float* plc = &vlc.x;
    float* pbp = &vbp.x; float* pib = &vib.x; float* poo = &voo.x;
    float* pol = &vol.x; float* polc = &volc.x; float* pf = &vf.x; float* pos = &vos.x;

    int t0 = 2 * i;
    #pragma unroll
    for (int j = 0; j < 2; ++j) {
        float c = cv[j], u1 = u1v[j], u2 = u2v[j];
        float zo = fmaf(c, p.koo, p.coo);
        float zi = fmaf(c, p.kib, fmaf(u1, p.kibu, p.cib));
        float zl = fmaf(u2, p.kol, p.col);
        float oo = fmaf(tanha(zo), p.hoo1, p.hoo1);
        float ib = fmaf(tanha(zi), 0.5f, 0.5f);
        float ol = fmaf(tanha(zl), p.hol1, p.hol1);
        bool  cp = (c > 0.0f);
        float olc  = cp ? fminf(ol, __fdividef(u2, c)) : ol;
        float olcc = cp ? fminf(ol * c, u2) : ol * c;
        float f   = 1.0f - oo - olc;
        float m   = (t0 + j >= tl) ? 1.0f : 0.0f;
        float bp  = ib * u1;
        float h   = fmaf(oo, c, bp);
        ph[j]   = m * h;
        pc[j]   = m * c;
        pl[j]   = m * (ol * c);
        plc[j]  = m * olcc;
        pbp[j]  = m * bp;
        pib[j]  = m * ib;
        poo[j]  = m * oo;
        pol[j]  = m * ol;
        polc[j] = m * olc;
        pf[j]   = m * f;
        pos[j]  = m * os;
    }

    stcs2(out + 2 * (size_t)i, vh);
    if (tl != 0)                                   // tl==0: scan's write IS m*c
        stcs2(out + B + 2 * (size_t)i, vc);
    stcs2(out + 2 * B + 2 * (size_t)i,  vl);
    stcs2(out + 3 * B + 2 * (size_t)i,  vlc);
    stcs2(out + 4 * B + 2 * (size_t)i,  vbp);
    stcs2(out + 5 * B + 2 * (size_t)i,  vib);
    stcs2(out + 6 * B + 2 * (size_t)i,  voo);
    stcs2(out + 7 * B + 2 * (size_t)i,  vol);
    stcs2(out + 8 * B + 2 * (size_t)i,  volc);
    stcs2(out + 9 * B + 2 * (size_t)i,  vf);
    stcs4(out + 10 * B + 4 * (size_t)i, make_float4(ph[0], pos[0], ph[1], pos[1]));
    stcs2(out + 12 * B + 2 * (size_t)i, vos);
}

// ---------------- launch ----------------
extern "C" void kernel_launch(void* const* d_in, const int* in_sizes, int n_in,
                              void* d_out, int out_size) {
    const float4* x4    = (const float4*)d_in[0];
    const int*    tl    = (const int*)   d_in[2];
    const float*  y_obs = (const float*) d_in[3];
    const float*  cmean = (const float*) d_in[4];
    const float*  cstd  = (const float*) d_in[5];
    const float*  wro   = (const float*) d_in[6];
    const float*  wrl   = (const float*) d_in[7];
    const float*  wrf   = (const float*) d_in[8];
    const float*  b0o   = (const float*) d_in[9];
    const float*  wb1o  = (const float*) d_in[10];
    const float*  b0l   = (const float*) d_in[11];
    const float*  wb2l  = (const float*) d_in[12];
    const float*  wb1u  = (const float*) d_in[13];
    const float*  b0u   = (const float*) d_in[14];
    float* out = (float*)d_out;

    float* c_out = out + (size_t)B_TOT;                   // stash c in c_n slot
    scanreduce_k<<<SGRID + RBLOCKS, SBLK>>>(x4, c_out, y_obs,
        cmean, cstd, wro, wrl, wrf, b0o, wb1o, b0l, wb2l, wb1u, b0u);

    // dependent launch with PDL: overlaps point_k prologue with primary tail
    cudaLaunchConfig_t cfg = {};
    cfg.gridDim  = dim3((B_TOT / 2 + 255) / 256);
    cfg.blockDim = dim3(256);
    cfg.stream   = 0;
    cudaLaunchAttribute attrs[1];
    attrs[0].id = cudaLaunchAttributeProgrammaticStreamSerialization;
    attrs[0].val.programmaticStreamSerializationAllowed = 1;
    cfg.attrs    = attrs;
    cfg.numAttrs = 1;
    cudaLaunchKernelEx(&cfg, point_k, x4, (float*)out, tl,
        cmean, cstd, wro, wrl, wrf, b0o, wb1o, b0l, wb2l, wb1u, b0u);
}